// round 8
// baseline (speedup 1.0000x reference)
#include <cuda_runtime.h>
#include <cuda_bf16.h>
#include <cstdint>

#define NTOK 4096
#define CEMB 128
#define NH 4
#define HD 32
#define NB 4
#define NBH (NB*NH)

// bf16 scratch [bh][n][32]; Q pre-scaled by log2(e)/sqrt(32)
__device__ __align__(16) unsigned short g_Qb[NBH * NTOK * HD];
__device__ __align__(16) unsigned short g_Kb[NBH * NTOK * HD];
__device__ __align__(16) unsigned short g_Vb[NBH * NTOK * HD];

__device__ __forceinline__ uint32_t smem_u32(const void* p) {
    uint32_t a;
    asm("{ .reg .u64 t; cvta.to.shared.u64 t, %1; cvt.u32.u64 %0, t; }" : "=r"(a) : "l"(p));
    return a;
}
__device__ __forceinline__ float ex2f(float x) {
    float y; asm("ex2.approx.ftz.f32 %0, %1;" : "=f"(y) : "f"(x)); return y;
}
__device__ __forceinline__ uint32_t pack_bf16x2(float hi, float lo) {
    uint32_t r; asm("cvt.rn.bf16x2.f32 %0, %1, %2;" : "=r"(r) : "f"(hi), "f"(lo)); return r;
}

#define LDSM4(r0,r1,r2,r3,addr) \
    asm volatile("ldmatrix.sync.aligned.m8n8.x4.shared.b16 {%0,%1,%2,%3}, [%4];" \
        : "=r"(r0),"=r"(r1),"=r"(r2),"=r"(r3) : "r"(addr))
#define LDSM4T(r0,r1,r2,r3,addr) \
    asm volatile("ldmatrix.sync.aligned.m8n8.x4.trans.shared.b16 {%0,%1,%2,%3}, [%4];" \
        : "=r"(r0),"=r"(r1),"=r"(r2),"=r"(r3) : "r"(addr))
#define MMA16816(d, a0,a1,a2,a3, b0,b1) \
    asm volatile("mma.sync.aligned.m16n8k16.row.col.f32.bf16.bf16.f32 " \
        "{%0,%1,%2,%3},{%4,%5,%6,%7},{%8,%9},{%0,%1,%2,%3};" \
        : "+f"((d)[0]),"+f"((d)[1]),"+f"((d)[2]),"+f"((d)[3]) \
        : "r"(a0),"r"(a1),"r"(a2),"r"(a3),"r"(b0),"r"(b1))

#define CP16(dst, src) \
    asm volatile("cp.async.cg.shared.global [%0], [%1], 16;" :: "r"(dst), "l"(src))
#define CPCOMMIT() asm volatile("cp.async.commit_group;" ::: "memory")
#define CPWAIT0()  asm volatile("cp.async.wait_group 0;" ::: "memory")
#define CPWAIT1()  asm volatile("cp.async.wait_group 1;" ::: "memory")

// ============================================================================
// Kernel 1: QKV projection via bf16 HMMA (unchanged from R7, ~8.5us).
// ============================================================================
__global__ __launch_bounds__(256) void qkv_kernel(
    const float* __restrict__ x,
    const float* __restrict__ W,
    const float* __restrict__ bias)
{
    __shared__ __align__(16) unsigned char xsm[64 * 272];
    __shared__ __align__(16) unsigned char wsm[64 * 272];

    const int t = threadIdx.x;
    const int wid = t >> 5, lane = t & 31;
    const int wm = wid >> 2, wn = wid & 3;
    const int b = blockIdx.z, n0 = blockIdx.y * 128, sect = blockIdx.x;
    const int jg0 = sect * 128;

    const uint32_t xsb = smem_u32(xsm);
    const uint32_t wsb = smem_u32(wsm);

    float acc[4][4][4];
    #pragma unroll
    for (int mt = 0; mt < 4; mt++)
        #pragma unroll
        for (int nt = 0; nt < 4; nt++)
            #pragma unroll
            for (int r = 0; r < 4; r++) acc[mt][nt][r] = 0.f;

    for (int c0 = 0; c0 < 128; c0 += 64) {
        if (c0) __syncthreads();
        #pragma unroll
        for (int r = 0; r < 8; r++) {
            int idx = t + r * 256;
            int cc = idx >> 5, nn4 = (idx & 31) * 4;
            float4 v = *(const float4*)(x + (size_t)b * CEMB * NTOK + (size_t)(c0 + cc) * NTOK + n0 + nn4);
            uint2 pv; pv.x = pack_bf16x2(v.y, v.x); pv.y = pack_bf16x2(v.w, v.z);
            *(uint2*)&xsm[cc * 272 + nn4 * 2] = pv;
            float4 w4 = *(const float4*)(W + (size_t)(c0 + cc) * 384 + jg0 + nn4);
            uint2 pw; pw.x = pack_bf16x2(w4.y, w4.x); pw.y = pack_bf16x2(w4.w, w4.z);
            *(uint2*)&wsm[cc * 272 + nn4 * 2] = pw;
        }
        __syncthreads();

        #pragma unroll
        for (int ks = 0; ks < 4; ks++) {
            int k0 = ks * 16;
            uint32_t af[4][4];
            #pragma unroll
            for (int mt = 0; mt < 4; mt++) {
                uint32_t a = xsb + (uint32_t)(k0 + (lane & 7) + ((lane >> 4) << 3)) * 272
                           + (uint32_t)(wm * 64 + mt * 16 + ((lane >> 3) & 1) * 8) * 2;
                LDSM4T(af[mt][0], af[mt][1], af[mt][2], af[mt][3], a);
            }
            uint32_t bfr[4][2];
            #pragma unroll
            for (int pr = 0; pr < 2; pr++) {
                uint32_t a = wsb + (uint32_t)(k0 + (lane & 7) + (((lane >> 3) & 1) << 3)) * 272
                           + (uint32_t)(wn * 32 + pr * 16 + ((lane >> 4) << 3)) * 2;
                uint32_t r0, r1, r2, r3;
                LDSM4T(r0, r1, r2, r3, a);
                bfr[2*pr][0] = r0; bfr[2*pr][1] = r1;
                bfr[2*pr+1][0] = r2; bfr[2*pr+1][1] = r3;
            }
            #pragma unroll
            for (int mt = 0; mt < 4; mt++)
                #pragma unroll
                for (int nt = 0; nt < 4; nt++)
                    MMA16816(acc[mt][nt], af[mt][0], af[mt][1], af[mt][2], af[mt][3],
                             bfr[nt][0], bfr[nt][1]);
        }
    }

    unsigned short* dst = (sect == 0) ? g_Qb : (sect == 1) ? g_Kb : g_Vb;
    const float sc = (sect == 0) ? 0.25504372842014487f : 1.0f;
    const int bh = b * NH + wn;
    #pragma unroll
    for (int nt = 0; nt < 4; nt++) {
        int jl = wn * 32 + nt * 8 + 2 * (lane & 3);
        float2 bv = *(const float2*)(bias + jg0 + jl);
        int d = jl & 31;
        #pragma unroll
        for (int mt = 0; mt < 4; mt++) {
            int row = n0 + wm * 64 + mt * 16 + (lane >> 2);
            uint32_t w0 = pack_bf16x2((acc[mt][nt][1] + bv.y) * sc, (acc[mt][nt][0] + bv.x) * sc);
            *(uint32_t*)(dst + ((size_t)bh * NTOK + row) * HD + d) = w0;
            uint32_t w1 = pack_bf16x2((acc[mt][nt][3] + bv.y) * sc, (acc[mt][nt][2] + bv.x) * sc);
            *(uint32_t*)(dst + ((size_t)bh * NTOK + row + 8) * HD + d) = w1;
        }
    }
}

// ============================================================================
// Kernel 2: bf16 HMMA flash attention, cross-tile software pipeline:
// 3-stage cp.async ring; per iter: S-MMA(kt+1) then {ex2(kt+1) || PV(kt)}.
// ============================================================================
__global__ __launch_bounds__(128, 4) void attn_kernel(
    const float* __restrict__ x,
    float* __restrict__ out)
{
    __shared__ __align__(128) unsigned char sm[3 * 10240];  // 3 stages x (K 64x80 | V 64x80)

    const int t = threadIdx.x, wid = t >> 5, lane = t & 31;
    const int bh = blockIdx.y, b = bh >> 2, head = bh & 3;
    const int q0 = blockIdx.x * 64;
    const uint32_t smb = smem_u32(sm);

    const char* kgb = (const char*)(g_Kb + (size_t)bh * NTOK * HD);
    const char* vgb = (const char*)(g_Vb + (size_t)bh * NTOK * HD);

    // issue cp for tiles 0 (stage0) and 1 (stage1)
    #pragma unroll
    for (int j = 0; j < 2; j++) {
        uint32_t base = smb + (uint32_t)j * 10240;
        const char* kg = kgb + (size_t)j * 4096;
        const char* vg = vgb + (size_t)j * 4096;
        #pragma unroll
        for (int r = 0; r < 2; r++) {
            int c = t + r * 128;
            uint32_t off = (uint32_t)(c >> 2) * 80 + (c & 3) * 16;
            CP16(base + off,        kg + c * 16);
            CP16(base + 5120 + off, vg + c * 16);
        }
        CPCOMMIT();
    }

    // stage Q in stage2 region (written later only by cp(tile2), issued after sync)
    {
        const uint4* qg = (const uint4*)(g_Qb + ((size_t)bh * NTOK + q0) * HD);
        #pragma unroll
        for (int r = 0; r < 2; r++) {
            int c = t + r * 128;
            *(uint4*)&sm[2 * 10240 + (c >> 2) * 80 + (c & 3) * 16] = qg[c];
        }
    }
    __syncthreads();
    uint32_t qa[2][4];
    #pragma unroll
    for (int kh = 0; kh < 2; kh++) {
        uint32_t a = smb + 2 * 10240 + (uint32_t)(16 * wid + (lane & 15)) * 80 + kh * 32 + (lane >> 4) * 16;
        LDSM4(qa[kh][0], qa[kh][1], qa[kh][2], qa[kh][3], a);
    }
    __syncthreads();

    float o[4][4];
    #pragma unroll
    for (int nt = 0; nt < 4; nt++)
        #pragma unroll
        for (int r = 0; r < 4; r++) o[nt][r] = 0.f;
    float lsum[2] = {0.f, 0.f};
    uint32_t pp[2][8][2];

    // prologue: wait tile0 (leave tile1 outstanding), compute S(0) -> pp[0]
    CPWAIT1();
    __syncthreads();
    {
        const uint32_t kst = smb;  // stage 0
        #pragma unroll
        for (int jp = 0; jp < 4; jp++) {
            uint32_t row = jp * 16 + (lane & 7) + ((lane >> 4) << 3);
            uint32_t ch = (lane >> 3) & 1;
            uint32_t b00[4], b01[4];
            LDSM4(b00[0], b00[1], b00[2], b00[3], kst + row * 80 + ch * 16);
            LDSM4(b01[0], b01[1], b01[2], b01[3], kst + row * 80 + (2 + ch) * 16);
            #pragma unroll
            for (int h = 0; h < 2; h++) {
                float s4[4] = {0.f, 0.f, 0.f, 0.f};
                MMA16816(s4, qa[0][0], qa[0][1], qa[0][2], qa[0][3], b00[2*h], b00[2*h+1]);
                MMA16816(s4, qa[1][0], qa[1][1], qa[1][2], qa[1][3], b01[2*h], b01[2*h+1]);
                float p0 = ex2f(s4[0]), p1 = ex2f(s4[1]), p2 = ex2f(s4[2]), p3 = ex2f(s4[3]);
                lsum[0] += p0 + p1;
                lsum[1] += p2 + p3;
                pp[0][2*jp+h][0] = pack_bf16x2(p1, p0);
                pp[0][2*jp+h][1] = pack_bf16x2(p3, p2);
            }
        }
    }

    #pragma unroll 2
    for (int kt = 0; kt < 64; kt++) {
        const int pc = kt & 1;
        const int st_v = kt % 3;

        if (kt < 63) CPWAIT0();       // tile kt+1 landed (only outstanding group)
        __syncthreads();              // all warps done with stage (kt+2)%3's old contents
        if (kt < 62) {                // prefetch tile kt+2 -> stage (kt+2)%3
            const int st_n = (kt + 2) % 3;
            const char* kg = kgb + (size_t)(kt + 2) * 4096;
            const char* vg = vgb + (size_t)(kt + 2) * 4096;
            uint32_t base = smb + (uint32_t)st_n * 10240;
            #pragma unroll
            for (int r = 0; r < 2; r++) {
                int c = t + r * 128;
                uint32_t off = (uint32_t)(c >> 2) * 80 + (c & 3) * 16;
                CP16(base + off,        kg + c * 16);
                CP16(base + 5120 + off, vg + c * 16);
            }
            CPCOMMIT();
        }

        // ---- S(kt+1): tensor ----
        float s32[8][4];
        if (kt < 63) {
            const uint32_t kst = smb + (uint32_t)((kt + 1) % 3) * 10240;
            #pragma unroll
            for (int jp = 0; jp < 4; jp++) {
                uint32_t row = jp * 16 + (lane & 7) + ((lane >> 4) << 3);
                uint32_t ch = (lane >> 3) & 1;
                uint32_t b00[4], b01[4];
                LDSM4(b00[0], b00[1], b00[2], b00[3], kst + row * 80 + ch * 16);
                LDSM4(b01[0], b01[1], b01[2], b01[3], kst + row * 80 + (2 + ch) * 16);
                #pragma unroll
                for (int h = 0; h < 2; h++) {
                    float* s4 = s32[2*jp+h];
                    s4[0] = s4[1] = s4[2] = s4[3] = 0.f;
                    MMA16816(s4, qa[0][0], qa[0][1], qa[0][2], qa[0][3], b00[2*h], b00[2*h+1]);
                    MMA16816(s4, qa[1][0], qa[1][1], qa[1][2], qa[1][3], b01[2*h], b01[2*h+1]);
                }
            }
        }

        // ---- interleave: ex2/pack(kt+1) on MUFU  ||  PV(kt) on tensor ----
        const uint32_t vst = smb + (uint32_t)st_v * 10240 + 5120;
        #pragma unroll
        for (int k4 = 0; k4 < 4; k4++) {
            uint32_t row = k4 * 16 + (lane & 7) + ((lane >> 3) & 1) * 8;
            uint32_t ch = lane >> 4;
            uint32_t v0[4], v1[4];
            LDSM4T(v0[0], v0[1], v0[2], v0[3], vst + row * 80 + ch * 16);
            LDSM4T(v1[0], v1[1], v1[2], v1[3], vst + row * 80 + (2 + ch) * 16);
            if (kt < 63) {
                #pragma unroll
                for (int cc = 0; cc < 2; cc++) {
                    int c = 2 * k4 + cc;
                    float p0 = ex2f(s32[c][0]), p1 = ex2f(s32[c][1]);
                    float p2 = ex2f(s32[c][2]), p3 = ex2f(s32[c][3]);
                    lsum[0] += p0 + p1;
                    lsum[1] += p2 + p3;
                    pp[pc ^ 1][c][0] = pack_bf16x2(p1, p0);
                    pp[pc ^ 1][c][1] = pack_bf16x2(p3, p2);
                }
            }
            uint32_t a0 = pp[pc][2*k4][0], a1 = pp[pc][2*k4][1];
            uint32_t a2 = pp[pc][2*k4+1][0], a3 = pp[pc][2*k4+1][1];
            MMA16816(o[0], a0, a1, a2, a3, v0[0], v0[1]);
            MMA16816(o[1], a0, a1, a2, a3, v0[2], v0[3]);
            MMA16816(o[2], a0, a1, a2, a3, v1[0], v1[1]);
            MMA16816(o[3], a0, a1, a2, a3, v1[2], v1[3]);
        }
    }

    // ---- epilogue ----
    float l0 = lsum[0];
    l0 += __shfl_xor_sync(0xffffffffu, l0, 1);
    l0 += __shfl_xor_sync(0xffffffffu, l0, 2);
    float l1 = lsum[1];
    l1 += __shfl_xor_sync(0xffffffffu, l1, 1);
    l1 += __shfl_xor_sync(0xffffffffu, l1, 2);
    float inv0 = 1.0f / l0, inv1 = 1.0f / l1;

    int r0 = q0 + 16 * wid + (lane >> 2);
    size_t base0 = (size_t)b * (CEMB * NTOK) + (size_t)r0 * CEMB + head * HD;
    size_t base1 = base0 + (size_t)8 * CEMB;

    #pragma unroll
    for (int nt = 0; nt < 4; nt++) {
        int col = 8 * nt + (lane & 3) * 2;
        float2 xv0 = *(const float2*)(x + base0 + col);
        float2 r;
        r.x = fmaf(o[nt][0], inv0, xv0.x);
        r.y = fmaf(o[nt][1], inv0, xv0.y);
        *(float2*)(out + base0 + col) = r;
        float2 xv1 = *(const float2*)(x + base1 + col);
        r.x = fmaf(o[nt][2], inv1, xv1.x);
        r.y = fmaf(o[nt][3], inv1, xv1.y);
        *(float2*)(out + base1 + col) = r;
    }
}

extern "C" void kernel_launch(void* const* d_in, const int* in_sizes, int n_in,
                              void* d_out, int out_size) {
    const float* x    = (const float*)d_in[0];
    const float* W    = (const float*)d_in[1];
    const float* bias = (const float*)d_in[2];
    float* out = (float*)d_out;

    dim3 g1(3, 32, NB);
    qkv_kernel<<<g1, 256>>>(x, W, bias);

    dim3 g2(NTOK / 64, NBH);
    attn_kernel<<<g2, 128>>>(x, out);
}